// round 2
// baseline (speedup 1.0000x reference)
#include <cuda_runtime.h>
#include <cuda_bf16.h>
#include <cstdint>

#define DIM 64
#define NCI_MAX 150000
#define FMA_MAX 100000
#define GATHER_BLOCKS 1184          // 148 SMs * 8 blocks = one full 64-warp wave
#define GATHER_TPB 256
#define CONV_BLOCKS 512

// ---------------- scratch (device globals: allocation-free rule) ----------------
__device__ __align__(128) __nv_bfloat16 g_Hn[NCI_MAX * DIM];   // 19.2 MB
__device__ __align__(128) __nv_bfloat16 g_Hm[NCI_MAX * DIM];   // 19.2 MB
__device__ __align__(128) __nv_bfloat16 g_Fb[FMA_MAX * DIM];   // 12.8 MB
__device__ float g_part[GATHER_BLOCKS];

// ---------------- packed f32x2 helpers ----------------
__device__ __forceinline__ unsigned long long pack2(float lo, float hi) {
    unsigned long long r;
    asm("mov.b64 %0, {%1, %2};" : "=l"(r) : "f"(lo), "f"(hi));
    return r;
}
__device__ __forceinline__ void unpack2(unsigned long long v, float& lo, float& hi) {
    asm("mov.b64 {%0, %1}, %2;" : "=f"(lo), "=f"(hi) : "l"(v));
}
__device__ __forceinline__ unsigned long long ffma2(unsigned long long a,
                                                    unsigned long long b,
                                                    unsigned long long c) {
    unsigned long long d;
    asm("fma.rn.f32x2 %0, %1, %2, %3;" : "=l"(d) : "l"(a), "l"(b), "l"(c));
    return d;
}
__device__ __forceinline__ unsigned long long fadd2(unsigned long long a,
                                                    unsigned long long b) {
    unsigned long long d;
    asm("add.rn.f32x2 %0, %1, %2;" : "=l"(d) : "l"(a), "l"(b));
    return d;
}
// bf16 pair word -> f32x2 (bf16 == top half of f32); optional sign flip
__device__ __forceinline__ unsigned long long b2f2(unsigned u) {
    unsigned lo = u << 16;
    unsigned hi = u & 0xffff0000u;
    unsigned long long r;
    asm("mov.b64 %0, {%1, %2};" : "=l"(r) : "r"(lo), "r"(hi));
    return r;
}
__device__ __forceinline__ unsigned long long b2f2_neg(unsigned u) {
    unsigned lo = (u << 16) ^ 0x80000000u;
    unsigned hi = (u & 0xffff0000u) ^ 0x80000000u;
    unsigned long long r;
    asm("mov.b64 %0, {%1, %2};" : "=l"(r) : "r"(lo), "r"(hi));
    return r;
}

// ---------------- kernel 1: Hn/Hm precompute + F convert (fused grid) ----------------
// Blocks [0, hBlocks): 64-row matmul tiles. Blocks [hBlocks, hBlocks+CONV_BLOCKS): F->bf16.
__global__ __launch_bounds__(128) void prep_kernel(
    const float* __restrict__ nci,
    const float* __restrict__ Mn,
    const float* __restrict__ Mm,
    const float* __restrict__ fmae,
    int nrows, int hBlocks, int f_elems)
{
    const int tid = threadIdx.x;

    if (blockIdx.x >= hBlocks) {
        // ---- F -> bf16 convert ----
        int cb = blockIdx.x - hBlocks;
        int stride = CONV_BLOCKS * 128;
        int nv = f_elems >> 2;
        for (int k = cb * 128 + tid; k < nv; k += stride) {
            float4 v = reinterpret_cast<const float4*>(fmae)[k];
            __nv_bfloat162* o = reinterpret_cast<__nv_bfloat162*>(g_Fb) + (size_t)k * 2;
            o[0] = __floats2bfloat162_rn(v.x, v.y);
            o[1] = __floats2bfloat162_rn(v.z, v.w);
        }
        return;
    }

    // ---- matmul tile ----
    extern __shared__ unsigned char smem[];
    float2 (*sM)[DIM + 1] = reinterpret_cast<float2(*)[DIM + 1]>(smem);
    float  (*sE)[DIM + 1] = reinterpret_cast<float(*)[DIM + 1]>(
        smem + sizeof(float2) * DIM * (DIM + 1));

    const int tx = tid & 7;          // col group
    const int ty = tid >> 3;         // row group (0..15)
    const int rowBase = blockIdx.x * 64;

    for (int idx = tid; idx < DIM * DIM; idx += 128) {
        int c = idx >> 6, j = idx & 63;
        sM[c][j] = make_float2(Mn[idx], Mm[idx]);
    }
    for (int idx = tid; idx < DIM * DIM; idx += 128) {
        int r = idx >> 6, j = idx & 63;
        int gr = rowBase + r;
        sE[r][j] = (gr < nrows) ? nci[(size_t)gr * DIM + j] : 0.0f;
    }
    __syncthreads();

    unsigned long long acc[8][4];
#pragma unroll
    for (int cc = 0; cc < 8; cc++)
#pragma unroll
        for (int rr = 0; rr < 4; rr++) acc[cc][rr] = 0ull;

#pragma unroll 4
    for (int j = 0; j < DIM; j++) {
        unsigned long long e2[4];
#pragma unroll
        for (int rr = 0; rr < 4; rr++) {
            float e = sE[ty * 4 + rr][j];
            e2[rr] = pack2(e, e);
        }
#pragma unroll
        for (int cc = 0; cc < 8; cc++) {
            float2 m = sM[tx + cc * 8][j];
            unsigned long long m2;
            asm("mov.b64 %0, {%1, %2};" : "=l"(m2) : "f"(m.x), "f"(m.y));
#pragma unroll
            for (int rr = 0; rr < 4; rr++)
                acc[cc][rr] = ffma2(m2, e2[rr], acc[cc][rr]);
        }
    }

#pragma unroll
    for (int rr = 0; rr < 4; rr++) {
        int r = rowBase + ty * 4 + rr;
        if (r < nrows) {
#pragma unroll
            for (int cc = 0; cc < 8; cc++) {
                int c = tx + cc * 8;
                float hn, hm;
                unpack2(acc[cc][rr], hn, hm);
                g_Hn[(size_t)r * DIM + c] = __float2bfloat16(hn);
                g_Hm[(size_t)r * DIM + c] = __float2bfloat16(hm);
            }
        }
    }
}

// ---------------- kernel 2: warp-cooperative gather + squared-diff ----------------
// One sample per warp-step: 32 lanes each load 4B (2 bf16) of the 128B row
// -> every warp LDG touches exactly one 128B line (1 L1tex wavefront).
__global__ __launch_bounds__(GATHER_TPB) void gather_loss(
    const int* __restrict__ pos_n,
    const int* __restrict__ pos_m,
    const int* __restrict__ pos_f,
    int B)
{
    const int lane = threadIdx.x & 31;
    const int warpLocal = threadIdx.x >> 5;
    const int wpb = GATHER_TPB >> 5;
    const int gw = blockIdx.x * wpb + warpLocal;
    const int nw = GATHER_BLOCKS * wpb;

    const char* baseHn = reinterpret_cast<const char*>(g_Hn) + lane * 4;
    const char* baseHm = reinterpret_cast<const char*>(g_Hm) + lane * 4;
    const char* baseFb = reinterpret_cast<const char*>(g_Fb) + lane * 4;

    unsigned long long accN = 0ull, accM = 0ull;

    for (int base = gw * 32; base < B; base += nw * 32) {
        int i = base + lane;
        int vn = 0, vm = 0, vf = 0;
        if (i < B) { vn = pos_n[i]; vm = pos_m[i]; vf = pos_f[i]; }
        int cnt = B - base; if (cnt > 32) cnt = 32;
#pragma unroll 4
        for (int s = 0; s < cnt; s++) {
            int an = __shfl_sync(0xffffffffu, vn, s);
            int am = __shfl_sync(0xffffffffu, vm, s);
            int af = __shfl_sync(0xffffffffu, vf, s);
            unsigned un = *reinterpret_cast<const unsigned*>(baseHn + an * 128);
            unsigned um = *reinterpret_cast<const unsigned*>(baseHm + am * 128);
            unsigned uf = *reinterpret_cast<const unsigned*>(baseFb + af * 128);
            unsigned long long xf = b2f2_neg(uf);
            unsigned long long dn = fadd2(b2f2(un), xf);
            unsigned long long dm = fadd2(b2f2(um), xf);
            accN = ffma2(dn, dn, accN);
            accM = ffma2(dm, dm, accM);
        }
    }

    float a0, a1, b0, b1;
    unpack2(accN, a0, a1);
    unpack2(accM, b0, b1);
    float acc = (a0 + a1) + (b0 + b1);

#pragma unroll
    for (int off = 16; off > 0; off >>= 1)
        acc += __shfl_xor_sync(0xffffffffu, acc, off);

    __shared__ float ws[GATHER_TPB / 32];
    if (lane == 0) ws[warpLocal] = acc;
    __syncthreads();
    if (warpLocal == 0) {
        float v = (lane < GATHER_TPB / 32) ? ws[lane] : 0.0f;
#pragma unroll
        for (int off = 4; off > 0; off >>= 1)
            v += __shfl_xor_sync(0xffffffffu, v, off);
        if (lane == 0) g_part[blockIdx.x] = v;
    }
}

// ---------------- kernel 3: deterministic final reduce ----------------
__global__ __launch_bounds__(128) void final_reduce(float* __restrict__ out, int nparts)
{
    float a = 0.0f;
    for (int i = threadIdx.x; i < nparts; i += 128) a += g_part[i];
#pragma unroll
    for (int off = 16; off > 0; off >>= 1)
        a += __shfl_xor_sync(0xffffffffu, a, off);
    __shared__ float ws[4];
    int lane = threadIdx.x & 31, wid = threadIdx.x >> 5;
    if (lane == 0) ws[wid] = a;
    __syncthreads();
    if (threadIdx.x == 0) out[0] = ws[0] + ws[1] + ws[2] + ws[3];
}

// ---------------- launch ----------------
extern "C" void kernel_launch(void* const* d_in, const int* in_sizes, int n_in,
                              void* d_out, int out_size)
{
    const int*   pos_n = (const int*)d_in[0];
    const int*   pos_m = (const int*)d_in[1];
    const int*   pos_f = (const int*)d_in[2];
    const float* nci   = (const float*)d_in[3];
    const float* fmae  = (const float*)d_in[4];
    const float* Mn    = (const float*)d_in[5];
    const float* Mm    = (const float*)d_in[6];

    int B = in_sizes[0];
    int nci_rows = in_sizes[3] / DIM;
    if (nci_rows > NCI_MAX) nci_rows = NCI_MAX;
    int f_elems = in_sizes[4];
    if (f_elems > FMA_MAX * DIM) f_elems = FMA_MAX * DIM;

    const int smem_bytes = (int)(sizeof(float2) * DIM * (DIM + 1) +
                                 sizeof(float)  * DIM * (DIM + 1));   // ~49.9 KB
    static bool attr_set = false;
    if (!attr_set) {
        cudaFuncSetAttribute(prep_kernel,
                             cudaFuncAttributeMaxDynamicSharedMemorySize, smem_bytes);
        attr_set = true;
    }

    int hBlocks = (nci_rows + 63) / 64;
    prep_kernel<<<hBlocks + CONV_BLOCKS, 128, smem_bytes>>>(
        nci, Mn, Mm, fmae, nci_rows, hBlocks, f_elems);
    gather_loss<<<GATHER_BLOCKS, GATHER_TPB>>>(pos_n, pos_m, pos_f, B);
    final_reduce<<<1, 128>>>((float*)d_out, GATHER_BLOCKS);
}

// round 4
// speedup vs baseline: 1.8784x; 1.8784x over previous
#include <cuda_runtime.h>
#include <cuda_bf16.h>
#include <cstdint>

#define DIM 64
#define NCI_MAX 150000
#define FMA_MAX 100000
#define GATHER_BLOCKS 2048
#define GATHER_TPB 256
#define CONV_BLOCKS 512

// ---------------- scratch (device globals: allocation-free rule) ----------------
__device__ __align__(128) __nv_bfloat16 g_Hn[NCI_MAX * DIM];   // 19.2 MB
__device__ __align__(128) __nv_bfloat16 g_Hm[NCI_MAX * DIM];   // 19.2 MB
__device__ __align__(128) __nv_bfloat16 g_Fb[FMA_MAX * DIM];   // 12.8 MB
__device__ float g_part[GATHER_BLOCKS];
__device__ unsigned g_ticket;

// ---------------- HMMA: m16n8k16 bf16 -> f32 ----------------
__device__ __forceinline__ void mma16816(float* d, const uint32_t* a, const uint32_t* b) {
    asm volatile(
        "mma.sync.aligned.m16n8k16.row.col.f32.bf16.bf16.f32 "
        "{%0,%1,%2,%3}, {%4,%5,%6,%7}, {%8,%9}, {%0,%1,%2,%3};"
        : "+f"(d[0]), "+f"(d[1]), "+f"(d[2]), "+f"(d[3])
        : "r"(a[0]), "r"(a[1]), "r"(a[2]), "r"(a[3]), "r"(b[0]), "r"(b[1]));
}

// shared tiles, padded to 72 bf16 (144 B) per row -> conflict-free fragment loads
#define SROW 72

// ---------------- kernel 1: HMMA precompute + F convert (fused grid) ----------------
// Blocks [0, hBlocks): D[128x128] = E_tile[128x64] @ [Mn;Mm]^T. Cols 0..63 -> Hn, 64..127 -> Hm.
// Blocks [hBlocks, hBlocks+CONV_BLOCKS): F -> bf16 convert.
__global__ __launch_bounds__(256) void prep_mma(
    const float* __restrict__ nci,
    const float* __restrict__ Mn,
    const float* __restrict__ Mm,
    const float* __restrict__ fmae,
    int nrows, int hBlocks, int f_elems)
{
    const int tid = threadIdx.x;

    if (blockIdx.x >= hBlocks) {
        // ---- F -> bf16 convert ----
        int cb = blockIdx.x - hBlocks;
        int stride = CONV_BLOCKS * 256;
        int nv = f_elems >> 2;
        for (int k = cb * 256 + tid; k < nv; k += stride) {
            float4 v = reinterpret_cast<const float4*>(fmae)[k];
            __nv_bfloat162* o = reinterpret_cast<__nv_bfloat162*>(g_Fb) + (size_t)k * 2;
            o[0] = __floats2bfloat162_rn(v.x, v.y);
            o[1] = __floats2bfloat162_rn(v.z, v.w);
        }
        return;
    }

    __shared__ __align__(16) __nv_bfloat16 sA[128][SROW];   // E tile   (18.4 KB)
    __shared__ __align__(16) __nv_bfloat16 sB[128][SROW];   // [Mn;Mm]  (18.4 KB)

    const int lane = tid & 31;
    const int w    = tid >> 5;          // warp 0..7
    const int gr   = lane >> 2;         // fragment row group 0..7
    const int c    = lane & 3;          // fragment col group 0..3
    const int rowBase = blockIdx.x * 128;

    // ---- stage A: E rows [rowBase, rowBase+128), f32 -> bf16 ----
#pragma unroll
    for (int it = 0; it < 8; it++) {
        int idx = it * 256 + tid;       // 2048 float4 chunks
        int r = idx >> 4;               // row in tile
        int cq = idx & 15;              // float4 within row
        int grow = rowBase + r;
        float4 v = (grow < nrows)
            ? reinterpret_cast<const float4*>(nci)[(size_t)grow * 16 + cq]
            : make_float4(0.f, 0.f, 0.f, 0.f);
        __nv_bfloat162 p0 = __floats2bfloat162_rn(v.x, v.y);
        __nv_bfloat162 p1 = __floats2bfloat162_rn(v.z, v.w);
        uint2 pk = make_uint2(*reinterpret_cast<uint32_t*>(&p0),
                              *reinterpret_cast<uint32_t*>(&p1));
        *reinterpret_cast<uint2*>(&sA[r][cq * 4]) = pk;
    }
    // ---- stage B: rows 0..63 = Mn, 64..127 = Mm ----
#pragma unroll
    for (int it = 0; it < 8; it++) {
        int idx = it * 256 + tid;
        int r = idx >> 4;
        int cq = idx & 15;
        const float4* src = reinterpret_cast<const float4*>(r < 64 ? Mn : Mm);
        float4 v = src[(size_t)(r & 63) * 16 + cq];
        __nv_bfloat162 p0 = __floats2bfloat162_rn(v.x, v.y);
        __nv_bfloat162 p1 = __floats2bfloat162_rn(v.z, v.w);
        uint2 pk = make_uint2(*reinterpret_cast<uint32_t*>(&p0),
                              *reinterpret_cast<uint32_t*>(&p1));
        *reinterpret_cast<uint2*>(&sB[r][cq * 4]) = pk;
    }
    __syncthreads();

    // ---- mma mainloop: warp w computes rows [w*16, w*16+16) x 128 cols ----
    float acc[16][4];
#pragma unroll
    for (int t = 0; t < 16; t++)
#pragma unroll
        for (int q = 0; q < 4; q++) acc[t][q] = 0.f;

#pragma unroll
    for (int kk = 0; kk < 4; kk++) {
        uint32_t a[4];
        const int ar0 = w * 16 + gr;
        const int ak  = kk * 16 + 2 * c;
        a[0] = *reinterpret_cast<const uint32_t*>(&sA[ar0][ak]);
        a[1] = *reinterpret_cast<const uint32_t*>(&sA[ar0 + 8][ak]);
        a[2] = *reinterpret_cast<const uint32_t*>(&sA[ar0][ak + 8]);
        a[3] = *reinterpret_cast<const uint32_t*>(&sA[ar0 + 8][ak + 8]);
#pragma unroll
        for (int t = 0; t < 16; t++) {
            uint32_t b[2];
            const int bn = t * 8 + gr;
            b[0] = *reinterpret_cast<const uint32_t*>(&sB[bn][ak]);
            b[1] = *reinterpret_cast<const uint32_t*>(&sB[bn][ak + 8]);
            mma16816(acc[t], a, b);
        }
    }

    // ---- epilogue: lane writes cols {2c,2c+1} of rows gr, gr+8 per n-tile ----
    const int r0 = rowBase + w * 16 + gr;
    const int r1 = r0 + 8;
#pragma unroll
    for (int t = 0; t < 16; t++) {
        int col = t * 8 + 2 * c;                  // 0..127
        __nv_bfloat16* tab = (col < 64) ? g_Hn : g_Hm;
        int cc = col & 63;
        __nv_bfloat162 v0 = __floats2bfloat162_rn(acc[t][0], acc[t][1]);
        __nv_bfloat162 v1 = __floats2bfloat162_rn(acc[t][2], acc[t][3]);
        if (r0 < nrows)
            *reinterpret_cast<__nv_bfloat162*>(tab + (size_t)r0 * 64 + cc) = v0;
        if (r1 < nrows)
            *reinterpret_cast<__nv_bfloat162*>(tab + (size_t)r1 * 64 + cc) = v1;
    }
}

// ---------------- bf16 pair -> two f32 (exact; ALU-pipe) ----------------
__device__ __forceinline__ float2 b2f(unsigned u) {
    return make_float2(__uint_as_float(u << 16), __uint_as_float(u & 0xffff0000u));
}

// ---------------- kernel 2: gather + squared-diff + fused final reduce ----------------
__global__ __launch_bounds__(GATHER_TPB) void gather_loss(
    const int* __restrict__ pos_n,
    const int* __restrict__ pos_m,
    const int* __restrict__ pos_f,
    int B, float* __restrict__ out)
{
    float acc = 0.0f;
    const int stride = GATHER_BLOCKS * GATHER_TPB;
    for (int i = blockIdx.x * GATHER_TPB + threadIdx.x; i < B; i += stride) {
        const uint4* hn = reinterpret_cast<const uint4*>(g_Hn + (size_t)pos_n[i] * DIM);
        const uint4* hm = reinterpret_cast<const uint4*>(g_Hm + (size_t)pos_m[i] * DIM);
        const uint4* fb = reinterpret_cast<const uint4*>(g_Fb + (size_t)pos_f[i] * DIM);
#pragma unroll
        for (int k = 0; k < 8; k++) {
            uint4 a = hn[k];
            uint4 b = hm[k];
            uint4 cde = fb[k];
            unsigned aw[4] = {a.x, a.y, a.z, a.w};
            unsigned bw[4] = {b.x, b.y, b.z, b.w};
            unsigned cw[4] = {cde.x, cde.y, cde.z, cde.w};
#pragma unroll
            for (int wv = 0; wv < 4; wv++) {
                float2 ha = b2f(aw[wv]);
                float2 hb = b2f(bw[wv]);
                float2 hf = b2f(cw[wv]);
                float d0 = ha.x - hf.x; acc = fmaf(d0, d0, acc);
                float d1 = ha.y - hf.y; acc = fmaf(d1, d1, acc);
                float d2 = hb.x - hf.x; acc = fmaf(d2, d2, acc);
                float d3 = hb.y - hf.y; acc = fmaf(d3, d3, acc);
            }
        }
    }

#pragma unroll
    for (int off = 16; off > 0; off >>= 1)
        acc += __shfl_xor_sync(0xffffffffu, acc, off);

    __shared__ float ws[GATHER_TPB / 32];
    __shared__ bool isLast;
    int lane = threadIdx.x & 31;
    int wid = threadIdx.x >> 5;
    if (lane == 0) ws[wid] = acc;
    __syncthreads();
    if (threadIdx.x == 0) {
        float v = 0.f;
#pragma unroll
        for (int k = 0; k < GATHER_TPB / 32; k++) v += ws[k];
        g_part[blockIdx.x] = v;
        __threadfence();
        unsigned prev = atomicInc(&g_ticket, GATHER_BLOCKS - 1);
        isLast = (prev == GATHER_BLOCKS - 1);
    }
    __syncthreads();

    if (isLast) {
        // deterministic: fixed per-thread strided order, fixed tree
        float a = 0.0f;
        for (int i = threadIdx.x; i < GATHER_BLOCKS; i += GATHER_TPB)
            a += g_part[i];
#pragma unroll
        for (int off = 16; off > 0; off >>= 1)
            a += __shfl_xor_sync(0xffffffffu, a, off);
        if (lane == 0) ws[wid] = a;
        __syncthreads();
        if (threadIdx.x == 0) {
            float v = 0.f;
#pragma unroll
            for (int k = 0; k < GATHER_TPB / 32; k++) v += ws[k];
            out[0] = v;
        }
    }
}

// ---------------- launch ----------------
extern "C" void kernel_launch(void* const* d_in, const int* in_sizes, int n_in,
                              void* d_out, int out_size)
{
    const int*   pos_n = (const int*)d_in[0];
    const int*   pos_m = (const int*)d_in[1];
    const int*   pos_f = (const int*)d_in[2];
    const float* nci   = (const float*)d_in[3];
    const float* fmae  = (const float*)d_in[4];
    const float* Mn    = (const float*)d_in[5];
    const float* Mm    = (const float*)d_in[6];

    int B = in_sizes[0];
    int nci_rows = in_sizes[3] / DIM;
    if (nci_rows > NCI_MAX) nci_rows = NCI_MAX;
    int f_elems = in_sizes[4];
    if (f_elems > FMA_MAX * DIM) f_elems = FMA_MAX * DIM;

    int hBlocks = (nci_rows + 127) / 128;
    prep_mma<<<hBlocks + CONV_BLOCKS, 256>>>(
        nci, Mn, Mm, fmae, nci_rows, hBlocks, f_elems);
    gather_loss<<<GATHER_BLOCKS, GATHER_TPB>>>(pos_n, pos_m, pos_f, B, (float*)d_out);
}

// round 5
// speedup vs baseline: 3.0039x; 1.5992x over previous
#include <cuda_runtime.h>
#include <cuda_bf16.h>
#include <cstdint>

#define DIM 64
#define NCI_MAX 150000
#define FMA_MAX 100000
#define GATHER_BLOCKS 2048
#define GATHER_TPB 256
#define CONV_BLOCKS 512

// ---------------- scratch (device globals: allocation-free rule) ----------------
__device__ __align__(128) __nv_bfloat16 g_Hn[NCI_MAX * DIM];   // 19.2 MB
__device__ __align__(128) __nv_bfloat16 g_Hm[NCI_MAX * DIM];   // 19.2 MB
__device__ __align__(128) __nv_bfloat16 g_Fb[FMA_MAX * DIM];   // 12.8 MB
__device__ float g_part[GATHER_BLOCKS];
__device__ unsigned g_ticket;

// ---------------- HMMA: m16n8k16 bf16 -> f32 ----------------
__device__ __forceinline__ void mma16816(float* d, const uint32_t* a, const uint32_t* b) {
    asm volatile(
        "mma.sync.aligned.m16n8k16.row.col.f32.bf16.bf16.f32 "
        "{%0,%1,%2,%3}, {%4,%5,%6,%7}, {%8,%9}, {%0,%1,%2,%3};"
        : "+f"(d[0]), "+f"(d[1]), "+f"(d[2]), "+f"(d[3])
        : "r"(a[0]), "r"(a[1]), "r"(a[2]), "r"(a[3]), "r"(b[0]), "r"(b[1]));
}

#define SROW 72   // padded bf16 row stride -> conflict-free fragment loads

// ---------------- packed f32x2 helpers ----------------
__device__ __forceinline__ unsigned long long ffma2(unsigned long long a,
                                                    unsigned long long b,
                                                    unsigned long long c) {
    unsigned long long d;
    asm("fma.rn.f32x2 %0, %1, %2, %3;" : "=l"(d) : "l"(a), "l"(b), "l"(c));
    return d;
}
__device__ __forceinline__ unsigned long long fadd2(unsigned long long a,
                                                    unsigned long long b) {
    unsigned long long d;
    asm("add.rn.f32x2 %0, %1, %2;" : "=l"(d) : "l"(a), "l"(b));
    return d;
}
__device__ __forceinline__ unsigned long long b2f2(unsigned u) {
    unsigned lo = u << 16;
    unsigned hi = u & 0xffff0000u;
    unsigned long long r;
    asm("mov.b64 %0, {%1, %2};" : "=l"(r) : "r"(lo), "r"(hi));
    return r;
}
__device__ __forceinline__ unsigned long long b2f2_neg(unsigned u) {
    unsigned lo = (u << 16) ^ 0x80000000u;
    unsigned hi = (u & 0xffff0000u) ^ 0x80000000u;
    unsigned long long r;
    asm("mov.b64 %0, {%1, %2};" : "=l"(r) : "r"(lo), "r"(hi));
    return r;
}
__device__ __forceinline__ void unpack2(unsigned long long v, float& lo, float& hi) {
    asm("mov.b64 {%0, %1}, %2;" : "=f"(lo), "=f"(hi) : "l"(v));
}

// ---------------- kernel 1: HMMA precompute + F convert (fused grid) ----------------
__global__ __launch_bounds__(256) void prep_mma(
    const float* __restrict__ nci,
    const float* __restrict__ Mn,
    const float* __restrict__ Mm,
    const float* __restrict__ fmae,
    int nrows, int hBlocks, int f_elems)
{
    const int tid = threadIdx.x;

    if (blockIdx.x >= hBlocks) {
        int cb = blockIdx.x - hBlocks;
        int stride = CONV_BLOCKS * 256;
        int nv = f_elems >> 2;
        for (int k = cb * 256 + tid; k < nv; k += stride) {
            float4 v = reinterpret_cast<const float4*>(fmae)[k];
            __nv_bfloat162* o = reinterpret_cast<__nv_bfloat162*>(g_Fb) + (size_t)k * 2;
            o[0] = __floats2bfloat162_rn(v.x, v.y);
            o[1] = __floats2bfloat162_rn(v.z, v.w);
        }
        return;
    }

    __shared__ __align__(16) __nv_bfloat16 sA[128][SROW];
    __shared__ __align__(16) __nv_bfloat16 sB[128][SROW];

    const int lane = tid & 31;
    const int w    = tid >> 5;
    const int gr   = lane >> 2;
    const int c    = lane & 3;
    const int rowBase = blockIdx.x * 128;

#pragma unroll
    for (int it = 0; it < 8; it++) {
        int idx = it * 256 + tid;
        int r = idx >> 4;
        int cq = idx & 15;
        int grow = rowBase + r;
        float4 v = (grow < nrows)
            ? reinterpret_cast<const float4*>(nci)[(size_t)grow * 16 + cq]
            : make_float4(0.f, 0.f, 0.f, 0.f);
        __nv_bfloat162 p0 = __floats2bfloat162_rn(v.x, v.y);
        __nv_bfloat162 p1 = __floats2bfloat162_rn(v.z, v.w);
        uint2 pk = make_uint2(*reinterpret_cast<uint32_t*>(&p0),
                              *reinterpret_cast<uint32_t*>(&p1));
        *reinterpret_cast<uint2*>(&sA[r][cq * 4]) = pk;
    }
#pragma unroll
    for (int it = 0; it < 8; it++) {
        int idx = it * 256 + tid;
        int r = idx >> 4;
        int cq = idx & 15;
        const float4* src = reinterpret_cast<const float4*>(r < 64 ? Mn : Mm);
        float4 v = src[(size_t)(r & 63) * 16 + cq];
        __nv_bfloat162 p0 = __floats2bfloat162_rn(v.x, v.y);
        __nv_bfloat162 p1 = __floats2bfloat162_rn(v.z, v.w);
        uint2 pk = make_uint2(*reinterpret_cast<uint32_t*>(&p0),
                              *reinterpret_cast<uint32_t*>(&p1));
        *reinterpret_cast<uint2*>(&sB[r][cq * 4]) = pk;
    }
    __syncthreads();

    float acc[16][4];
#pragma unroll
    for (int t = 0; t < 16; t++)
#pragma unroll
        for (int q = 0; q < 4; q++) acc[t][q] = 0.f;

#pragma unroll
    for (int kk = 0; kk < 4; kk++) {
        uint32_t a[4];
        const int ar0 = w * 16 + gr;
        const int ak  = kk * 16 + 2 * c;
        a[0] = *reinterpret_cast<const uint32_t*>(&sA[ar0][ak]);
        a[1] = *reinterpret_cast<const uint32_t*>(&sA[ar0 + 8][ak]);
        a[2] = *reinterpret_cast<const uint32_t*>(&sA[ar0][ak + 8]);
        a[3] = *reinterpret_cast<const uint32_t*>(&sA[ar0 + 8][ak + 8]);
#pragma unroll
        for (int t = 0; t < 16; t++) {
            uint32_t b[2];
            const int bn = t * 8 + gr;
            b[0] = *reinterpret_cast<const uint32_t*>(&sB[bn][ak]);
            b[1] = *reinterpret_cast<const uint32_t*>(&sB[bn][ak + 8]);
            mma16816(acc[t], a, b);
        }
    }

    const int r0 = rowBase + w * 16 + gr;
    const int r1 = r0 + 8;
#pragma unroll
    for (int t = 0; t < 16; t++) {
        int col = t * 8 + 2 * c;
        __nv_bfloat16* tab = (col < 64) ? g_Hn : g_Hm;
        int cc = col & 63;
        __nv_bfloat162 v0 = __floats2bfloat162_rn(acc[t][0], acc[t][1]);
        __nv_bfloat162 v1 = __floats2bfloat162_rn(acc[t][2], acc[t][3]);
        if (r0 < nrows)
            *reinterpret_cast<__nv_bfloat162*>(tab + (size_t)r0 * 64 + cc) = v0;
        if (r1 < nrows)
            *reinterpret_cast<__nv_bfloat162*>(tab + (size_t)r1 * 64 + cc) = v1;
    }
}

// ---------------- kernel 2: 8-lane-cooperative gather + fused reduce ----------------
// 8 lanes share one sample's 128B row: each warp-LDG.128 serves 4 samples and
// touches exactly 4 cache lines (4 L1tex wavefronts), each line read once.
__global__ __launch_bounds__(GATHER_TPB) void gather_loss(
    const int* __restrict__ pos_n,
    const int* __restrict__ pos_m,
    const int* __restrict__ pos_f,
    int B, float* __restrict__ out)
{
    const int lane = threadIdx.x & 31;
    const int wloc = threadIdx.x >> 5;
    const int warp = blockIdx.x * (GATHER_TPB >> 5) + wloc;
    const int nwarp = GATHER_BLOCKS * (GATHER_TPB >> 5);
    const int grp = lane >> 3;          // sample-group 0..3 within warp-step
    const int sub = lane & 7;           // 16B chunk within 128B row

    const char* baseHn = reinterpret_cast<const char*>(g_Hn) + sub * 16;
    const char* baseHm = reinterpret_cast<const char*>(g_Hm) + sub * 16;
    const char* baseFb = reinterpret_cast<const char*>(g_Fb) + sub * 16;

    unsigned long long accN0 = 0ull, accN1 = 0ull, accM0 = 0ull, accM1 = 0ull;

    for (int base = warp * 32; base < B; base += nwarp * 32) {
        int i = base + lane;
        int vn = 0, vm = 0, vf = 0;
        if (i < B) { vn = pos_n[i]; vm = pos_m[i]; vf = pos_f[i]; }
        const int cnt = (B - base < 32) ? (B - base) : 32;
#pragma unroll
        for (int t = 0; t < 8; t++) {
            const int s = t * 4 + grp;
            int an = __shfl_sync(0xffffffffu, vn, s);
            int am = __shfl_sync(0xffffffffu, vm, s);
            int af = __shfl_sync(0xffffffffu, vf, s);
            if (s < cnt) {
                uint4 a = *reinterpret_cast<const uint4*>(baseHn + an * 128);
                uint4 b = *reinterpret_cast<const uint4*>(baseHm + am * 128);
                uint4 f = *reinterpret_cast<const uint4*>(baseFb + af * 128);
                unsigned long long f0 = b2f2_neg(f.x);
                unsigned long long f1 = b2f2_neg(f.y);
                unsigned long long f2 = b2f2_neg(f.z);
                unsigned long long f3 = b2f2_neg(f.w);
                unsigned long long d;
                d = fadd2(b2f2(a.x), f0); accN0 = ffma2(d, d, accN0);
                d = fadd2(b2f2(a.y), f1); accN1 = ffma2(d, d, accN1);
                d = fadd2(b2f2(a.z), f2); accN0 = ffma2(d, d, accN0);
                d = fadd2(b2f2(a.w), f3); accN1 = ffma2(d, d, accN1);
                d = fadd2(b2f2(b.x), f0); accM0 = ffma2(d, d, accM0);
                d = fadd2(b2f2(b.y), f1); accM1 = ffma2(d, d, accM1);
                d = fadd2(b2f2(b.z), f2); accM0 = ffma2(d, d, accM0);
                d = fadd2(b2f2(b.w), f3); accM1 = ffma2(d, d, accM1);
            }
        }
    }

    unsigned long long accA = fadd2(accN0, accN1);
    unsigned long long accB = fadd2(accM0, accM1);
    float a0, a1, b0, b1;
    unpack2(accA, a0, a1);
    unpack2(accB, b0, b1);
    float acc = (a0 + a1) + (b0 + b1);

#pragma unroll
    for (int off = 16; off > 0; off >>= 1)
        acc += __shfl_xor_sync(0xffffffffu, acc, off);

    __shared__ float ws[GATHER_TPB / 32];
    __shared__ bool isLast;
    if (lane == 0) ws[wloc] = acc;
    __syncthreads();
    if (threadIdx.x == 0) {
        float v = 0.f;
#pragma unroll
        for (int k = 0; k < GATHER_TPB / 32; k++) v += ws[k];
        g_part[blockIdx.x] = v;
        __threadfence();
        unsigned prev = atomicInc(&g_ticket, GATHER_BLOCKS - 1);
        isLast = (prev == GATHER_BLOCKS - 1);
    }
    __syncthreads();

    if (isLast) {
        float a = 0.0f;
        for (int i = threadIdx.x; i < GATHER_BLOCKS; i += GATHER_TPB)
            a += g_part[i];
#pragma unroll
        for (int off = 16; off > 0; off >>= 1)
            a += __shfl_xor_sync(0xffffffffu, a, off);
        if (lane == 0) ws[wloc] = a;
        __syncthreads();
        if (threadIdx.x == 0) {
            float v = 0.f;
#pragma unroll
            for (int k = 0; k < GATHER_TPB / 32; k++) v += ws[k];
            out[0] = v;
        }
    }
}

// ---------------- launch ----------------
extern "C" void kernel_launch(void* const* d_in, const int* in_sizes, int n_in,
                              void* d_out, int out_size)
{
    const int*   pos_n = (const int*)d_in[0];
    const int*   pos_m = (const int*)d_in[1];
    const int*   pos_f = (const int*)d_in[2];
    const float* nci   = (const float*)d_in[3];
    const float* fmae  = (const float*)d_in[4];
    const float* Mn    = (const float*)d_in[5];
    const float* Mm    = (const float*)d_in[6];

    int B = in_sizes[0];
    int nci_rows = in_sizes[3] / DIM;
    if (nci_rows > NCI_MAX) nci_rows = NCI_MAX;
    int f_elems = in_sizes[4];
    if (f_elems > FMA_MAX * DIM) f_elems = FMA_MAX * DIM;

    int hBlocks = (nci_rows + 127) / 128;
    prep_mma<<<hBlocks + CONV_BLOCKS, 256>>>(
        nci, Mn, Mm, fmae, nci_rows, hBlocks, f_elems);
    gather_loss<<<GATHER_BLOCKS, GATHER_TPB>>>(pos_n, pos_m, pos_f, B, (float*)d_out);
}